// round 3
// baseline (speedup 1.0000x reference)
#include <cuda_runtime.h>
#include <cuda_bf16.h>
#include <stdint.h>

#define RBOX   500000
#define KCLS   10
#define NSCAL  (RBOX * 11)          // 5,500,000 floats in scores
#define NV4    (NSCAL / 4)          // 1,375,000 float4s (exact)
#define TTOP   2048
#define SCORE_T 0.05f
#define NMS_T   0.5f
#define CLS_OFF 3001.0f
#define IMG_W   1920.0f
#define IMG_H   1080.0f

// histogram of float bits >> 13, range (0.05, 1.0)
#define HBASE  125542u              // 0x3D4CCCCD >> 13  (bits of 0.05f)
#define HBINS  4506
#define CAP    4096
#define ECAP   4096

#define HBLK   336                  // ceil(NV4 / 4096) pass-1 blocks (512 thr x 8 f4)
#define NSUB   42969                // ceil(NV4 / 32)  subtiles (128 floats each)

// ---------------- device scratch ----------------
__device__ unsigned int       g_hist[HBINS];
__device__ unsigned int       g_tilemax[HBLK * 128];   // max fg bits per subtile
__device__ unsigned int       g_cutbin;
__device__ unsigned int       g_cnt;
__device__ unsigned long long g_keys[CAP];
__device__ float              g_nbox[TTOP * 4];
__device__ float              g_obox[TTOP * 4];
__device__ float              g_oscore[TTOP];
__device__ unsigned int       g_ecnt;
__device__ unsigned int       g_edges[ECAP];

// ---------------- kernel 1: histogram + per-subtile max (pass 1) ----------------
__global__ void __launch_bounds__(512) k_hist(const float* __restrict__ scores,
                                              const float* __restrict__ center) {
    __shared__ unsigned sh[HBINS];      // 18 KB
    int t = threadIdx.x;
    for (int b = t; b < HBINS; b += 512) sh[b] = 0u;
    __syncthreads();

    const float4* s4 = (const float4*)scores;
    unsigned lane = t & 31u, w = (unsigned)t >> 5;
    unsigned base = blockIdx.x * 4096u;

    #pragma unroll
    for (int u = 0; u < 8; u++) {
        unsigned q = base + u * 512u + (unsigned)t;
        unsigned maxb = 0u;
        if (q < NV4) {
            float4 v = __ldg(&s4[q]);
            unsigned gi = q * 4u;
            #pragma unroll
            for (int e = 0; e < 4; e++) {
                float val = (e == 0) ? v.x : (e == 1) ? v.y : (e == 2) ? v.z : v.w;
                unsigned g = gi + e;
                unsigned r = g / 11u;
                unsigned c = g - r * 11u;
                if (c != 0u) {
                    float fg = val * center[r];
                    if (fg > SCORE_T) {
                        unsigned bits = __float_as_uint(fg);
                        unsigned bin = (bits >> 13) - HBASE;
                        if (bin >= HBINS) bin = HBINS - 1;
                        atomicAdd(&sh[bin], 1u);
                        if (bits > maxb) maxb = bits;
                    }
                }
            }
        }
        // warp-reduce max over this 32-f4 (128-float) contiguous subtile
        #pragma unroll
        for (int off = 16; off > 0; off >>= 1)
            maxb = max(maxb, __shfl_xor_sync(0xFFFFFFFFu, maxb, off));
        unsigned st = blockIdx.x * 128u + (unsigned)u * 16u + w;
        if (lane == 0u && st < NSUB) g_tilemax[st] = maxb;
    }
    __syncthreads();
    for (int b = t; b < HBINS; b += 512) {
        unsigned v = sh[b];
        if (v) atomicAdd(&g_hist[b], v);
    }
}

// ---------------- kernel 2: suffix scan -> cut bin; re-zero hist & cnt ----------------
__global__ void k_scan() {
    __shared__ unsigned part[1024];
    __shared__ unsigned sincl[1024];
    int t = threadIdx.x;
    const int CH = 5;
    int lo = t * CH;
    int hi = lo + CH; if (hi > HBINS) hi = HBINS; if (lo > HBINS) lo = HBINS;
    unsigned p = 0u;
    unsigned loc[CH];
    for (int b = lo; b < hi; b++) { loc[b - lo] = g_hist[b]; p += loc[b - lo]; }
    part[t] = p; sincl[t] = p;
    __syncthreads();
    for (int off = 1; off < 1024; off <<= 1) {
        unsigned v = (t + off < 1024) ? sincl[t + off] : 0u;
        __syncthreads();
        sincl[t] += v;
        __syncthreads();
    }
    unsigned total = sincl[0];
    if (total >= TTOP) {
        unsigned above = sincl[t] - part[t];
        if (above < TTOP && sincl[t] >= TTOP) {
            unsigned run = above;
            for (int b = hi - 1; b >= lo; b--) {
                run += loc[b - lo];
                if (run >= TTOP) { g_cutbin = (unsigned)b; break; }
            }
        }
    } else if (t == 0) {
        g_cutbin = 0u;
    }
    __syncthreads();
    // restore state for next replay (graph-deterministic)
    for (int b = t; b < HBINS; b += 1024) g_hist[b] = 0u;
    if (t == 0) g_cnt = 0u;
}

// ---------------- kernel 3: compact (pass 2, warp-per-subtile with skip) ----------------
__global__ void __launch_bounds__(256) k_compact(const float* __restrict__ scores,
                                                 const float* __restrict__ center) {
    unsigned warpid = (blockIdx.x * 256u + threadIdx.x) >> 5;
    unsigned lane = threadIdx.x & 31u;
    if (warpid >= NSUB) return;
    unsigned cut = g_cutbin;
    unsigned maxb = g_tilemax[warpid];
    // skip subtile unless its max candidate reaches the cut bin
    if ((maxb >> 13) < HBASE + cut) return;

    unsigned q = warpid * 32u + lane;
    if (q >= NV4) return;
    float4 v = __ldg(&((const float4*)scores)[q]);
    unsigned gi = q * 4u;
    #pragma unroll
    for (int e = 0; e < 4; e++) {
        float val = (e == 0) ? v.x : (e == 1) ? v.y : (e == 2) ? v.z : v.w;
        unsigned g = gi + e;
        unsigned r = g / 11u;
        unsigned c = g - r * 11u;
        if (c != 0u) {
            float fg = val * center[r];
            if (fg > SCORE_T) {
                unsigned bits = __float_as_uint(fg);
                if ((bits >> 13) >= HBASE + cut) {
                    unsigned j = r * 10u + (c - 1u);
                    unsigned pos = atomicAdd(&g_cnt, 1u);
                    if (pos < CAP) {
                        g_keys[pos] = ((unsigned long long)bits << 32) |
                                      (unsigned long long)(0xFFFFFFFFu - j);
                    }
                }
            }
        }
    }
}

// ---------------- kernel 4: bitonic sort + gather boxes ----------------
__global__ void k_sortgather(const float* __restrict__ boxes) {
    __shared__ unsigned long long sk[CAP];  // 32 KB
    int t = threadIdx.x;
    unsigned n = g_cnt; if (n > CAP) n = CAP;
    if (t == 0) g_ecnt = 0u;                // reset for k_edges (every replay)
    for (int i = t; i < CAP; i += 1024) sk[i] = (i < (int)n) ? g_keys[i] : 0ull;
    __syncthreads();
    for (unsigned k = 2; k <= CAP; k <<= 1) {
        for (unsigned jj = k >> 1; jj > 0; jj >>= 1) {
            for (unsigned i = t; i < CAP; i += 1024) {
                unsigned ixj = i ^ jj;
                if (ixj > i) {
                    bool up = ((i & k) != 0);   // descending overall
                    unsigned long long a = sk[i], b = sk[ixj];
                    bool sw = up ? (a > b) : (a < b);
                    if (sw) { sk[i] = b; sk[ixj] = a; }
                }
            }
            __syncthreads();
        }
    }
    for (int i = t; i < TTOP; i += 1024) {
        unsigned long long key = sk[i];
        float s = __uint_as_float((unsigned)(key >> 32));
        float b0 = 0.f, b1 = 0.f, b2 = 0.f, b3 = 0.f;
        float n0 = 0.f, n1 = 0.f, n2 = 0.f, n3 = 0.f, sc = 0.f;
        if (s > SCORE_T) {
            unsigned j = 0xFFFFFFFFu - (unsigned)(key & 0xFFFFFFFFull);
            unsigned r = j / 10u;
            unsigned cls = j - r * 10u;
            float x1 = boxes[r * 4 + 0], y1 = boxes[r * 4 + 1];
            float x2 = boxes[r * 4 + 2], y2 = boxes[r * 4 + 3];
            b0 = fminf(fmaxf(x1, 0.f), IMG_W);
            b1 = fminf(fmaxf(y1, 0.f), IMG_H);
            b2 = fminf(fmaxf(x2, 0.f), IMG_W);
            b3 = fminf(fmaxf(y2, 0.f), IMG_H);
            float off = (float)cls * CLS_OFF;
            n0 = b0 + off; n1 = b1 + off; n2 = b2 + off; n3 = b3 + off;
            sc = s;
        }
        g_obox[i * 4 + 0] = b0; g_obox[i * 4 + 1] = b1;
        g_obox[i * 4 + 2] = b2; g_obox[i * 4 + 3] = b3;
        g_nbox[i * 4 + 0] = n0; g_nbox[i * 4 + 1] = n1;
        g_nbox[i * 4 + 2] = n2; g_nbox[i * 4 + 3] = n3;
        g_oscore[i] = sc;
    }
}

// ---------------- kernel 5: pairwise IoU -> sparse suppression edges ----------------
__global__ void k_edges() {
    int bi = blockIdx.y, bj = blockIdx.x;
    if (bj < bi) return;
    __shared__ float jb[64 * 4];
    int t = threadIdx.x;                    // 64 threads
    int jbase = bj * 64;
    for (int q = t; q < 256; q += 64) jb[q] = g_nbox[jbase * 4 + q];
    __syncthreads();
    int i = bi * 64 + t;
    float ax1 = g_nbox[i * 4 + 0], ay1 = g_nbox[i * 4 + 1];
    float ax2 = g_nbox[i * 4 + 2], ay2 = g_nbox[i * 4 + 3];
    float aarea = fmaxf(ax2 - ax1, 0.f) * fmaxf(ay2 - ay1, 0.f);
    for (int q = 0; q < 64; q++) {
        int j = jbase + q;
        if (j <= i) continue;
        float bx1 = jb[q * 4 + 0], by1 = jb[q * 4 + 1];
        float bx2 = jb[q * 4 + 2], by2 = jb[q * 4 + 3];
        float barea = fmaxf(bx2 - bx1, 0.f) * fmaxf(by2 - by1, 0.f);
        float w = fmaxf(fminf(ax2, bx2) - fmaxf(ax1, bx1), 0.f);
        float h = fmaxf(fminf(ay2, by2) - fmaxf(ay1, by1), 0.f);
        float inter = w * h;
        float iou = inter / (aarea + barea - inter + 1e-9f);
        if (iou > NMS_T) {
            unsigned pos = atomicAdd(&g_ecnt, 1u);
            if (pos < ECAP) g_edges[pos] = ((unsigned)i << 16) | (unsigned)j;
        }
    }
}

// ---------------- kernel 6: sort edges, greedy replay, write output ----------------
__global__ void k_final(float* __restrict__ out) {
    __shared__ unsigned se[ECAP];
    __shared__ unsigned char keep[TTOP];
    int t = threadIdx.x;
    unsigned E = g_ecnt; if (E > ECAP) E = ECAP;
    for (int i = t; i < ECAP; i += 1024) se[i] = (i < (int)E) ? g_edges[i] : 0xFFFFFFFFu;
    for (int i = t; i < TTOP; i += 1024) keep[i] = (g_oscore[i] > SCORE_T) ? 1 : 0;
    __syncthreads();

    if (E > 1) {
        unsigned P = 2;
        while (P < E) P <<= 1;
        for (unsigned k = 2; k <= P; k <<= 1) {
            for (unsigned jj = k >> 1; jj > 0; jj >>= 1) {
                for (unsigned i = t; i < P; i += 1024) {
                    unsigned ixj = i ^ jj;
                    if (ixj > i) {
                        bool up = ((i & k) == 0);
                        unsigned a = se[i], b = se[ixj];
                        bool sw = up ? (a > b) : (a < b);
                        if (sw) { se[i] = b; se[ixj] = a; }
                    }
                }
                __syncthreads();
            }
        }
    }
    if (t == 0) {
        for (unsigned e = 0; e < E; e++) {
            unsigned v = se[e];
            unsigned i = v >> 16, j = v & 0xFFFFu;
            if (keep[i]) keep[j] = 0;
        }
    }
    __syncthreads();
    for (int i = t; i < TTOP; i += 1024) {
        bool kp = keep[i] != 0;
        out[i * 5 + 0] = kp ? g_obox[i * 4 + 0] : 0.f;
        out[i * 5 + 1] = kp ? g_obox[i * 4 + 1] : 0.f;
        out[i * 5 + 2] = kp ? g_obox[i * 4 + 2] : 0.f;
        out[i * 5 + 3] = kp ? g_obox[i * 4 + 3] : 0.f;
        out[i * 5 + 4] = kp ? g_oscore[i] : 0.f;
    }
}

// ---------------- launch ----------------
extern "C" void kernel_launch(void* const* d_in, const int* in_sizes, int n_in,
                              void* d_out, int out_size) {
    const float* boxes  = nullptr;
    const float* scores = nullptr;
    const float* center = nullptr;
    for (int i = 0; i < n_in; i++) {
        if (in_sizes[i] == RBOX * 4)       boxes  = (const float*)d_in[i];
        else if (in_sizes[i] == RBOX * 11) scores = (const float*)d_in[i];
        else if (in_sizes[i] == RBOX)      center = (const float*)d_in[i];
    }
    if (!boxes)  boxes  = (const float*)d_in[0];
    if (!scores) scores = (const float*)d_in[1];
    if (!center) center = (const float*)d_in[2];
    float* out = (float*)d_out;

    k_hist<<<HBLK, 512>>>(scores, center);
    k_scan<<<1, 1024>>>();
    k_compact<<<(NSUB * 32 + 255) / 256, 256>>>(scores, center);
    k_sortgather<<<1, 1024>>>(boxes);
    k_edges<<<dim3(32, 32), 64>>>();
    k_final<<<1, 1024>>>(out);
}

// round 4
// speedup vs baseline: 1.7084x; 1.7084x over previous
#include <cuda_runtime.h>
#include <cuda_bf16.h>
#include <stdint.h>

#define RBOX   500000
#define KCLS   10
#define NSCAL  (RBOX * 11)          // 5,500,000 floats in scores
#define NV4    (NSCAL / 4)          // 1,375,000 float4s (exact)
#define TTOP   2048
#define SCORE_T 0.05f
#define NMS_T   0.5f
#define CLS_OFF 3001.0f
#define IMG_W   1920.0f
#define IMG_H   1080.0f

// histogram of float bits >> 13, range (0.05, 1.0)
#define HBASE  125542u              // 0x3D4CCCCD >> 13  (bits of 0.05f)
#define HBINS  4506
#define CAP    4096
#define ECAP   4096

#define HBLK   336                  // ceil(NV4 / 4096) pass-1 blocks (512 thr x 8 f4)
#define NSUB   42969                // ceil(NV4 / 32)  subtiles (128 floats each)

// ---------------- device scratch ----------------
__device__ unsigned int       g_hist[HBINS];
__device__ unsigned int       g_tilemax[HBLK * 128];
__device__ unsigned int       g_cutbin;
__device__ unsigned int       g_cnt;
__device__ unsigned long long g_keys[CAP];
__device__ float              g_nbox[TTOP * 4];
__device__ float              g_obox[TTOP * 4];
__device__ float              g_oscore[TTOP];
__device__ unsigned int       g_ecnt;
__device__ unsigned int       g_edges[ECAP];

// ---------------- kernel 1: histogram + per-subtile max (pass 1) ----------------
__global__ void __launch_bounds__(512) k_hist(const float* __restrict__ scores,
                                              const float* __restrict__ center) {
    __shared__ unsigned sh[HBINS];      // 18 KB
    int t = threadIdx.x;
    for (int b = t; b < HBINS; b += 512) sh[b] = 0u;
    __syncthreads();

    const float4* s4 = (const float4*)scores;
    unsigned lane = t & 31u, w = (unsigned)t >> 5;
    unsigned base = blockIdx.x * 4096u;

    #pragma unroll
    for (int u = 0; u < 8; u++) {
        unsigned q = base + u * 512u + (unsigned)t;
        unsigned maxb = 0u;
        if (q < NV4) {
            float4 v = __ldg(&s4[q]);
            unsigned gi = q * 4u;
            #pragma unroll
            for (int e = 0; e < 4; e++) {
                float val = (e == 0) ? v.x : (e == 1) ? v.y : (e == 2) ? v.z : v.w;
                unsigned g = gi + e;
                unsigned r = g / 11u;
                unsigned c = g - r * 11u;
                if (c != 0u) {
                    float fg = val * center[r];
                    if (fg > SCORE_T) {
                        unsigned bits = __float_as_uint(fg);
                        unsigned bin = (bits >> 13) - HBASE;
                        if (bin >= HBINS) bin = HBINS - 1;
                        atomicAdd(&sh[bin], 1u);
                        if (bits > maxb) maxb = bits;
                    }
                }
            }
        }
        #pragma unroll
        for (int off = 16; off > 0; off >>= 1)
            maxb = max(maxb, __shfl_xor_sync(0xFFFFFFFFu, maxb, off));
        unsigned st = blockIdx.x * 128u + (unsigned)u * 16u + w;
        if (lane == 0u && st < NSUB) g_tilemax[st] = maxb;
    }
    __syncthreads();
    for (int b = t; b < HBINS; b += 512) {
        unsigned v = sh[b];
        if (v) atomicAdd(&g_hist[b], v);
    }
}

// ---------------- kernel 2: suffix scan -> cut bin; reset state; zero outputs ----------------
__global__ void k_scan() {
    __shared__ unsigned part[1024];
    __shared__ unsigned sincl[1024];
    int t = threadIdx.x;
    const int CH = 5;
    int lo = t * CH;
    int hi = lo + CH; if (hi > HBINS) hi = HBINS; if (lo > HBINS) lo = HBINS;
    unsigned p = 0u;
    unsigned loc[CH];
    for (int b = lo; b < hi; b++) { loc[b - lo] = g_hist[b]; p += loc[b - lo]; }
    part[t] = p; sincl[t] = p;
    __syncthreads();
    for (int off = 1; off < 1024; off <<= 1) {
        unsigned v = (t + off < 1024) ? sincl[t + off] : 0u;
        __syncthreads();
        sincl[t] += v;
        __syncthreads();
    }
    unsigned total = sincl[0];
    if (total >= TTOP) {
        unsigned above = sincl[t] - part[t];
        if (above < TTOP && sincl[t] >= TTOP) {
            unsigned run = above;
            for (int b = hi - 1; b >= lo; b--) {
                run += loc[b - lo];
                if (run >= TTOP) { g_cutbin = (unsigned)b; break; }
            }
        }
    } else if (t == 0) {
        g_cutbin = 0u;
    }
    __syncthreads();
    // restore / init state for this replay
    for (int b = t; b < HBINS; b += 1024) g_hist[b] = 0u;
    for (int i = t; i < TTOP * 4; i += 1024) { g_obox[i] = 0.f; g_nbox[i] = 0.f; }
    for (int i = t; i < TTOP; i += 1024) g_oscore[i] = 0.f;
    if (t == 0) { g_cnt = 0u; g_ecnt = 0u; }
}

// ---------------- kernel 3: compact (pass 2, warp-per-subtile with skip) ----------------
__global__ void __launch_bounds__(256) k_compact(const float* __restrict__ scores,
                                                 const float* __restrict__ center) {
    unsigned warpid = (blockIdx.x * 256u + threadIdx.x) >> 5;
    unsigned lane = threadIdx.x & 31u;
    if (warpid >= NSUB) return;
    unsigned cut = g_cutbin;
    unsigned maxb = g_tilemax[warpid];
    if ((maxb >> 13) < HBASE + cut) return;

    unsigned q = warpid * 32u + lane;
    if (q >= NV4) return;
    float4 v = __ldg(&((const float4*)scores)[q]);
    unsigned gi = q * 4u;
    #pragma unroll
    for (int e = 0; e < 4; e++) {
        float val = (e == 0) ? v.x : (e == 1) ? v.y : (e == 2) ? v.z : v.w;
        unsigned g = gi + e;
        unsigned r = g / 11u;
        unsigned c = g - r * 11u;
        if (c != 0u) {
            float fg = val * center[r];
            if (fg > SCORE_T) {
                unsigned bits = __float_as_uint(fg);
                if ((bits >> 13) >= HBASE + cut) {
                    unsigned j = r * 10u + (c - 1u);
                    unsigned pos = atomicAdd(&g_cnt, 1u);
                    if (pos < CAP) {
                        g_keys[pos] = ((unsigned long long)bits << 32) |
                                      (unsigned long long)(0xFFFFFFFFu - j);
                    }
                }
            }
        }
    }
}

// ---------------- kernel 4: rank-by-count + gather + scatter (replaces sort) ----------------
// rank_i = #{keys > key_i}; keys are unique -> bijection onto [0, n).
// Warp per candidate; lane 0 of winning warps gathers box and scatters to rank.
__global__ void __launch_bounds__(1024) k_rank(const float* __restrict__ boxes) {
    unsigned n = g_cnt; if (n > CAP) n = CAP;
    unsigned wid = (blockIdx.x * 1024u + threadIdx.x) >> 5;
    unsigned lane = threadIdx.x & 31u;
    if (wid >= n) return;
    unsigned long long mykey = g_keys[wid];
    unsigned cnt = 0u;
    for (unsigned j = lane; j < n; j += 32u)
        cnt += (g_keys[j] > mykey) ? 1u : 0u;
    #pragma unroll
    for (int off = 16; off > 0; off >>= 1)
        cnt += __shfl_xor_sync(0xFFFFFFFFu, cnt, off);
    if (lane == 0u && cnt < TTOP) {
        unsigned rank = cnt;
        unsigned j = 0xFFFFFFFFu - (unsigned)(mykey & 0xFFFFFFFFull);
        float s = __uint_as_float((unsigned)(mykey >> 32));
        unsigned r = j / 10u;
        unsigned cls = j - r * 10u;
        float x1 = boxes[r * 4 + 0], y1 = boxes[r * 4 + 1];
        float x2 = boxes[r * 4 + 2], y2 = boxes[r * 4 + 3];
        float b0 = fminf(fmaxf(x1, 0.f), IMG_W);
        float b1 = fminf(fmaxf(y1, 0.f), IMG_H);
        float b2 = fminf(fmaxf(x2, 0.f), IMG_W);
        float b3 = fminf(fmaxf(y2, 0.f), IMG_H);
        float off2 = (float)cls * CLS_OFF;
        g_obox[rank * 4 + 0] = b0; g_obox[rank * 4 + 1] = b1;
        g_obox[rank * 4 + 2] = b2; g_obox[rank * 4 + 3] = b3;
        g_nbox[rank * 4 + 0] = b0 + off2; g_nbox[rank * 4 + 1] = b1 + off2;
        g_nbox[rank * 4 + 2] = b2 + off2; g_nbox[rank * 4 + 3] = b3 + off2;
        g_oscore[rank] = s;
    }
}

// ---------------- kernel 5: pairwise IoU -> sparse suppression edges ----------------
__global__ void k_edges() {
    int bi = blockIdx.y, bj = blockIdx.x;
    if (bj < bi) return;
    __shared__ float jb[64 * 4];
    int t = threadIdx.x;                    // 64 threads
    int jbase = bj * 64;
    for (int q = t; q < 256; q += 64) jb[q] = g_nbox[jbase * 4 + q];
    __syncthreads();
    int i = bi * 64 + t;
    float ax1 = g_nbox[i * 4 + 0], ay1 = g_nbox[i * 4 + 1];
    float ax2 = g_nbox[i * 4 + 2], ay2 = g_nbox[i * 4 + 3];
    float aarea = fmaxf(ax2 - ax1, 0.f) * fmaxf(ay2 - ay1, 0.f);
    for (int q = 0; q < 64; q++) {
        int j = jbase + q;
        if (j <= i) continue;
        float bx1 = jb[q * 4 + 0], by1 = jb[q * 4 + 1];
        float bx2 = jb[q * 4 + 2], by2 = jb[q * 4 + 3];
        float barea = fmaxf(bx2 - bx1, 0.f) * fmaxf(by2 - by1, 0.f);
        float w = fmaxf(fminf(ax2, bx2) - fmaxf(ax1, bx1), 0.f);
        float h = fmaxf(fminf(ay2, by2) - fmaxf(ay1, by1), 0.f);
        float inter = w * h;
        float iou = inter / (aarea + barea - inter + 1e-9f);
        if (iou > NMS_T) {
            unsigned pos = atomicAdd(&g_ecnt, 1u);
            if (pos < ECAP) g_edges[pos] = ((unsigned)i << 16) | (unsigned)j;
        }
    }
}

// ---------------- kernel 6: sort edges, greedy replay, write output ----------------
__global__ void k_final(float* __restrict__ out) {
    __shared__ unsigned se[ECAP];
    __shared__ unsigned char keep[TTOP];
    int t = threadIdx.x;
    unsigned E = g_ecnt; if (E > ECAP) E = ECAP;
    for (int i = t; i < ECAP; i += 1024) se[i] = (i < (int)E) ? g_edges[i] : 0xFFFFFFFFu;
    for (int i = t; i < TTOP; i += 1024) keep[i] = (g_oscore[i] > SCORE_T) ? 1 : 0;
    __syncthreads();

    if (E > 1) {
        unsigned P = 2;
        while (P < E) P <<= 1;
        for (unsigned k = 2; k <= P; k <<= 1) {
            for (unsigned jj = k >> 1; jj > 0; jj >>= 1) {
                for (unsigned i = t; i < P; i += 1024) {
                    unsigned ixj = i ^ jj;
                    if (ixj > i) {
                        bool up = ((i & k) == 0);
                        unsigned a = se[i], b = se[ixj];
                        bool sw = up ? (a > b) : (a < b);
                        if (sw) { se[i] = b; se[ixj] = a; }
                    }
                }
                __syncthreads();
            }
        }
    }
    if (t == 0) {
        for (unsigned e = 0; e < E; e++) {
            unsigned v = se[e];
            unsigned i = v >> 16, j = v & 0xFFFFu;
            if (keep[i]) keep[j] = 0;
        }
    }
    __syncthreads();
    for (int i = t; i < TTOP; i += 1024) {
        bool kp = keep[i] != 0;
        out[i * 5 + 0] = kp ? g_obox[i * 4 + 0] : 0.f;
        out[i * 5 + 1] = kp ? g_obox[i * 4 + 1] : 0.f;
        out[i * 5 + 2] = kp ? g_obox[i * 4 + 2] : 0.f;
        out[i * 5 + 3] = kp ? g_obox[i * 4 + 3] : 0.f;
        out[i * 5 + 4] = kp ? g_oscore[i] : 0.f;
    }
}

// ---------------- launch ----------------
extern "C" void kernel_launch(void* const* d_in, const int* in_sizes, int n_in,
                              void* d_out, int out_size) {
    const float* boxes  = nullptr;
    const float* scores = nullptr;
    const float* center = nullptr;
    for (int i = 0; i < n_in; i++) {
        if (in_sizes[i] == RBOX * 4)       boxes  = (const float*)d_in[i];
        else if (in_sizes[i] == RBOX * 11) scores = (const float*)d_in[i];
        else if (in_sizes[i] == RBOX)      center = (const float*)d_in[i];
    }
    if (!boxes)  boxes  = (const float*)d_in[0];
    if (!scores) scores = (const float*)d_in[1];
    if (!center) center = (const float*)d_in[2];
    float* out = (float*)d_out;

    k_hist<<<HBLK, 512>>>(scores, center);
    k_scan<<<1, 1024>>>();
    k_compact<<<(NSUB * 32 + 255) / 256, 256>>>(scores, center);
    k_rank<<<(CAP + 31) / 32, 1024>>>(boxes);   // 128 blocks x 32 warps = 4096 warps
    k_edges<<<dim3(32, 32), 64>>>();
    k_final<<<1, 1024>>>(out);
}